// round 1
// baseline (speedup 1.0000x reference)
#include <cuda_runtime.h>

typedef unsigned long long ull;

#define NB 16
#define NC 128
#define NS 16384
#define NK 64
#define XROW 132   // smem row stride (floats) for both X and A tiles

__device__ float g_cwt[NC*NK];    // codewords transposed [c][k]
__device__ float g_cw2[NK];       // ||cw_k||^2
__device__ float g_e[NB*NK*NC];   // aggregated residual (cross part)
__device__ float g_asum[NB*NK];   // sum_s a[b,s,k]
__device__ float g_mean[NK];
__device__ float g_rstd[NK];
__device__ float g_scale[NB*NC];

__device__ __forceinline__ ull pack2(float lo, float hi){
    ull r; asm("mov.b64 %0, {%1, %2};" : "=l"(r) : "f"(lo), "f"(hi)); return r;
}
__device__ __forceinline__ void unpack2(ull v, float& lo, float& hi){
    asm("mov.b64 {%0, %1}, %2;" : "=f"(lo), "=f"(hi) : "l"(v));
}
__device__ __forceinline__ void ffma2(ull& acc, ull a, ull b){
    asm("fma.rn.f32x2 %0, %1, %2, %0;" : "+l"(acc) : "l"(a), "l"(b));
}

// ---------------------------------------------------------------- prep
__global__ void k_prep(const float* __restrict__ cw){
    int i = blockIdx.x*256 + threadIdx.x;
    if (i < NB*NK*NC) g_e[i] = 0.f;
    if (i < NB*NK)    g_asum[i] = 0.f;
    if (i < NK*NC){ int k = i >> 7, c = i & 127; g_cwt[c*NK + k] = cw[i]; }
    if (i < NK){
        float s = 0.f;
        for (int c = 0; c < NC; c++){ float v = cw[i*NC + c]; s = fmaf(v, v, s); }
        g_cw2[i] = s;
    }
}

// ---------------------------------------------------------------- encode
// Grid: 1024 blocks (16 b x 64 tiles of 256 s), 256 threads, 2 subtiles of 128 s.
__global__ void __launch_bounds__(256,2) k_encode(const float* __restrict__ x,
                                                  const float* __restrict__ smo){
    extern __shared__ float sh[];
    float* Xs    = sh;                 // NC * XROW  (x tile, [c][s])
    float* At    = sh + NC*XROW;       // NK * XROW  (logits -> a, [k][s])
    float* x2S   = At + NK*XROW;       // 128
    float* asumS = x2S + NC;           // 64

    int tid  = threadIdx.x;
    int b    = blockIdx.x >> 6;
    int tile = blockIdx.x & 63;
    const float* xb = x + (long)b * ((long)NC * NS);

    int ts = tid >> 3, tk = tid & 7;    // cross-GEMM: 4 s x 8 k per thread
    int kg = tid >> 4, cg = tid & 15;   // e-GEMM:     4 k x 8 c per thread

    if (tid < NK) asumS[tid] = 0.f;

    ull eacc[16];
    #pragma unroll
    for (int i = 0; i < 16; i++) eacc[i] = 0ULL;

    for (int sub = 0; sub < 2; sub++){
        int s0 = tile*256 + sub*128;
        __syncthreads();
        // stage X tile [c][s], float4 coalesced
        for (int i = tid; i < NC*32; i += 256){
            int c = i >> 5, q = i & 31;
            float4 v = *(const float4*)(xb + (long)c*NS + s0 + 4*q);
            *(float4*)&Xs[c*XROW + 4*q] = v;
        }
        __syncthreads();
        // x2 per s (lane-contiguous -> conflict free)
        if (tid < 128){
            float s = 0.f;
            #pragma unroll 8
            for (int c = 0; c < NC; c++){ float v = Xs[c*XROW + tid]; s = fmaf(v, v, s); }
            x2S[tid] = s;
        }
        __syncthreads();
        // cross GEMM -> logits (FFMA2, pairs over k)
        {
            ull acc[16];
            #pragma unroll
            for (int i = 0; i < 16; i++) acc[i] = 0ULL;
            const float4* cwt4 = (const float4*)g_cwt;
            #pragma unroll 4
            for (int c = 0; c < NC; c++){
                float4 xv = *(const float4*)&Xs[c*XROW + 4*ts];
                float4 ca = __ldg(&cwt4[c*16 + 2*tk]);
                float4 cb = __ldg(&cwt4[c*16 + 2*tk + 1]);
                ull cp0 = pack2(ca.x, ca.y), cp1 = pack2(ca.z, ca.w);
                ull cp2 = pack2(cb.x, cb.y), cp3 = pack2(cb.z, cb.w);
                ull x0 = pack2(xv.x, xv.x), x1 = pack2(xv.y, xv.y);
                ull x2d = pack2(xv.z, xv.z), x3 = pack2(xv.w, xv.w);
                ffma2(acc[0],  x0,  cp0); ffma2(acc[1],  x0,  cp1); ffma2(acc[2],  x0,  cp2); ffma2(acc[3],  x0,  cp3);
                ffma2(acc[4],  x1,  cp0); ffma2(acc[5],  x1,  cp1); ffma2(acc[6],  x1,  cp2); ffma2(acc[7],  x1,  cp3);
                ffma2(acc[8],  x2d, cp0); ffma2(acc[9],  x2d, cp1); ffma2(acc[10], x2d, cp2); ffma2(acc[11], x2d, cp3);
                ffma2(acc[12], x3,  cp0); ffma2(acc[13], x3,  cp1); ffma2(acc[14], x3,  cp2); ffma2(acc[15], x3,  cp3);
            }
            const float4* sm4 = (const float4*)smo;
            const float4* c24 = (const float4*)g_cw2;
            float4 sa = sm4[2*tk], sb = sm4[2*tk+1];
            float4 ba = c24[2*tk], bb = c24[2*tk+1];
            float smk[8] = {sa.x,sa.y,sa.z,sa.w, sb.x,sb.y,sb.z,sb.w};
            float c2k[8] = {ba.x,ba.y,ba.z,ba.w, bb.x,bb.y,bb.z,bb.w};
            #pragma unroll
            for (int j = 0; j < 4; j++){
                float xx = x2S[4*ts + j];
                #pragma unroll
                for (int m = 0; m < 4; m++){
                    float lo, hi; unpack2(acc[j*4+m], lo, hi);
                    int k0 = 8*tk + 2*m;
                    At[k0*XROW + 4*ts + j]     = smk[2*m]   * ((xx + c2k[2*m])   - 2.f*lo);
                    At[(k0+1)*XROW + 4*ts + j] = smk[2*m+1] * ((xx + c2k[2*m+1]) - 2.f*hi);
                }
            }
        }
        __syncthreads();
        // softmax over k (warp per s, 2 k per lane)
        {
            int w = tid >> 5, lane = tid & 31;
            for (int s = w; s < 128; s += 8){
                float l0 = At[lane*XROW + s];
                float l1 = At[(lane+32)*XROW + s];
                float mx = fmaxf(l0, l1);
                #pragma unroll
                for (int o = 16; o > 0; o >>= 1) mx = fmaxf(mx, __shfl_xor_sync(0xffffffffu, mx, o));
                float e0 = __expf(l0 - mx), e1 = __expf(l1 - mx);
                float ss = e0 + e1;
                #pragma unroll
                for (int o = 16; o > 0; o >>= 1) ss += __shfl_xor_sync(0xffffffffu, ss, o);
                float inv = 1.f / ss;
                At[lane*XROW + s]      = e0*inv;
                At[(lane+32)*XROW + s] = e1*inv;
            }
        }
        __syncthreads();
        // asum per k
        if (tid < NK){
            float s = 0.f;
            const float4* ar = (const float4*)&At[tid*XROW];
            #pragma unroll 8
            for (int q = 0; q < 32; q++){ float4 v = ar[q]; s += (v.x+v.y)+(v.z+v.w); }
            asumS[tid] += s;
        }
        // e GEMM (FFMA2, pairs over c; c strided by 16 -> 2-phase LDS)
        {
            const float4* At4 = (const float4*)At;
            const float4* Xs4 = (const float4*)Xs;
            for (int q = 0; q < 32; q++){
                float4 a0 = At4[(4*kg+0)*33 + q];
                float4 a1 = At4[(4*kg+1)*33 + q];
                float4 a2 = At4[(4*kg+2)*33 + q];
                float4 a3 = At4[(4*kg+3)*33 + q];
                float4 v0 = Xs4[(cg      )*33 + q];
                float4 v1 = Xs4[(cg + 16 )*33 + q];
                float4 v2 = Xs4[(cg + 32 )*33 + q];
                float4 v3 = Xs4[(cg + 48 )*33 + q];
                float4 v4 = Xs4[(cg + 64 )*33 + q];
                float4 v5 = Xs4[(cg + 80 )*33 + q];
                float4 v6 = Xs4[(cg + 96 )*33 + q];
                float4 v7 = Xs4[(cg + 112)*33 + q];
                #define P4STEP(CMP) do{ \
                    ull xp0 = pack2(v0.CMP, v1.CMP); \
                    ull xp1 = pack2(v2.CMP, v3.CMP); \
                    ull xp2 = pack2(v4.CMP, v5.CMP); \
                    ull xp3 = pack2(v6.CMP, v7.CMP); \
                    ull ad; \
                    ad = pack2(a0.CMP, a0.CMP); ffma2(eacc[0], ad, xp0);  ffma2(eacc[1], ad, xp1);  ffma2(eacc[2], ad, xp2);  ffma2(eacc[3], ad, xp3); \
                    ad = pack2(a1.CMP, a1.CMP); ffma2(eacc[4], ad, xp0);  ffma2(eacc[5], ad, xp1);  ffma2(eacc[6], ad, xp2);  ffma2(eacc[7], ad, xp3); \
                    ad = pack2(a2.CMP, a2.CMP); ffma2(eacc[8], ad, xp0);  ffma2(eacc[9], ad, xp1);  ffma2(eacc[10], ad, xp2); ffma2(eacc[11], ad, xp3); \
                    ad = pack2(a3.CMP, a3.CMP); ffma2(eacc[12], ad, xp0); ffma2(eacc[13], ad, xp1); ffma2(eacc[14], ad, xp2); ffma2(eacc[15], ad, xp3); \
                } while(0)
                P4STEP(x); P4STEP(y); P4STEP(z); P4STEP(w);
                #undef P4STEP
            }
        }
    }
    // block-level partials -> global (RED.ADD, 8192+64 per block)
    float* ge = g_e + b*NK*NC;
    #pragma unroll
    for (int i = 0; i < 4; i++){
        int k = 4*kg + i;
        #pragma unroll
        for (int jp = 0; jp < 4; jp++){
            float lo, hi; unpack2(eacc[i*4+jp], lo, hi);
            int c0 = cg + 32*jp;
            atomicAdd(&ge[k*NC + c0],      lo);
            atomicAdd(&ge[k*NC + c0 + 16], hi);
        }
    }
    if (tid < NK) atomicAdd(&g_asum[b*NK + tid], asumS[tid]);
}

// ---------------------------------------------------------------- BN stats
__global__ void k_bnstats(const float* __restrict__ cw){
    int k = blockIdx.x, tid = threadIdx.x;
    float s = 0.f, s2 = 0.f;
    for (int i = tid; i < NB*NC; i += 256){
        int b = i >> 7, c = i & 127;
        float ev = g_e[b*NK*NC + k*NC + c] - g_asum[b*NK + k]*cw[k*NC + c];
        s += ev; s2 = fmaf(ev, ev, s2);
    }
    __shared__ float rs[8], rs2[8];
    #pragma unroll
    for (int o = 16; o > 0; o >>= 1){
        s  += __shfl_xor_sync(0xffffffffu, s,  o);
        s2 += __shfl_xor_sync(0xffffffffu, s2, o);
    }
    int w = tid >> 5;
    if ((tid & 31) == 0){ rs[w] = s; rs2[w] = s2; }
    __syncthreads();
    if (tid == 0){
        float S = 0.f, S2 = 0.f;
        for (int i = 0; i < 8; i++){ S += rs[i]; S2 += rs2[i]; }
        float mean = S * (1.f/2048.f);
        float var  = S2 * (1.f/2048.f) - mean*mean;
        g_mean[k] = mean;
        g_rstd[k] = rsqrtf(var + 1e-5f);
    }
}

// ---------------------------------------------------------------- BN+relu+mean+FC+sigmoid
__global__ void k_scalecalc(const float* __restrict__ cw,  const float* __restrict__ bnw,
                            const float* __restrict__ bnb, const float* __restrict__ fcw,
                            const float* __restrict__ fcb){
    int b = blockIdx.x, c = threadIdx.x; // 128 threads
    float acc = 0.f;
    for (int k = 0; k < NK; k++){
        float ev = g_e[b*NK*NC + k*NC + c] - g_asum[b*NK + k]*cw[k*NC + c];
        float bn = (ev - g_mean[k]) * g_rstd[k] * bnw[k] + bnb[k];
        acc += fmaxf(bn, 0.f);
    }
    __shared__ float en[NC];
    en[c] = acc * (1.f/64.f);
    __syncthreads();
    float o = fcb[c];
    for (int j = 0; j < NC; j++) o = fmaf(en[j], fcw[c*NC + j], o);
    g_scale[b*NC + c] = 1.f / (1.f + expf(-o));
}

// ---------------------------------------------------------------- apply scale
__global__ void k_apply(const float* __restrict__ x, float* __restrict__ out){
    long i = (long)blockIdx.x*256 + threadIdx.x;   // float4 index
    float4 v = ((const float4*)x)[i];
    float sc = g_scale[i >> 12];                    // 4096 float4 per (b,c)
    float4 o; o.x = v.x*sc; o.y = v.y*sc; o.z = v.z*sc; o.w = v.w*sc;
    ((float4*)out)[i] = o;
}

// ---------------------------------------------------------------- launch
extern "C" void kernel_launch(void* const* d_in, const int* in_sizes, int n_in,
                              void* d_out, int out_size){
    const float* x   = (const float*)d_in[0];
    const float* cw  = (const float*)d_in[1];
    const float* smo = (const float*)d_in[2];
    const float* bnw = (const float*)d_in[3];
    const float* bnb = (const float*)d_in[4];
    const float* fcw = (const float*)d_in[5];
    const float* fcb = (const float*)d_in[6];
    float* out = (float*)d_out;

    const int smem_bytes = (NC*XROW + NK*XROW + NC + NK) * 4;  // 102144
    cudaFuncSetAttribute(k_encode, cudaFuncAttributeMaxDynamicSharedMemorySize, smem_bytes);

    k_prep<<<516, 256>>>(cw);
    k_encode<<<1024, 256, smem_bytes>>>(x, smo);
    k_bnstats<<<64, 256>>>(cw);
    k_scalecalc<<<16, 128>>>(cw, bnw, bnb, fcw, fcb);
    k_apply<<<32768, 256>>>(x, out);
}